// round 1
// baseline (speedup 1.0000x reference)
#include <cuda_runtime.h>
#include <cstdint>

// ---------------------------------------------------------------------------
// MentionLabeler: out[b,i,j] = sum_d relu(a[b,i,d] + c[b,j,d]) * W2[d] + b2
//   a = emb @ W1[:768] + b1,  c = emb @ W1[768:]
// Shapes: emb (4,512,768) f32, W1 (1536,256), b1 (256), W2 (256,1), b2 (1)
// Output: (4,512,512) f32
// ---------------------------------------------------------------------------

#define B_   4
#define N_   512
#define H_   768
#define HID_ 256
#define M_   (B_ * N_)        // 2048 rows of emb

// Scratch (device globals: allocation-free)
__device__ float g_a[M_ * HID_];   // emb @ Wa + b1
__device__ float g_c[M_ * HID_];   // emb @ Wb

// Packed fp32x2 FMA (Blackwell). 2x fp32 FMA throughput on the fma pipe.
__device__ __forceinline__ float2 ffma2(float2 a, float2 b, float2 c) {
    union F2U { float2 f; unsigned long long u; };
    F2U A, Bv, C, D;
    A.f = a; Bv.f = b; C.f = c;
    asm("fma.rn.f32x2 %0, %1, %2, %3;"
        : "=l"(D.u) : "l"(A.u), "l"(Bv.u), "l"(C.u));
    return D.f;
}

// ---------------------------------------------------------------------------
// Kernel 1: fp32 GEMM  out[m,n] = sum_k emb[m,k] * W[k,n] (+ b1[n] for half 0)
// Tiles: BM=BN=64, BK=16, 256 threads, 4x4 per thread, FFMA2 packed over n.
// ---------------------------------------------------------------------------
#define GBM 64
#define GBN 64
#define GBK 16

__global__ void __launch_bounds__(256, 2)
gemm_kernel(const float* __restrict__ emb, const float* __restrict__ W1,
            const float* __restrict__ b1)
{
    const int half = blockIdx.z;                 // 0 -> a (+b1), 1 -> c
    const float* __restrict__ W = W1 + half * (H_ * HID_);
    float* __restrict__ out = half ? g_c : g_a;

    const int m0 = blockIdx.y * GBM;
    const int n0 = blockIdx.x * GBN;

    __shared__ float As[GBK][GBM + 4];   // k-major, +4 pad keeps 16B align
    __shared__ float Bs[GBK][GBN + 4];

    const int t  = threadIdx.x;          // 256
    const int tx = t & 15;               // n group
    const int ty = t >> 4;               // m group

    float2 acc[4][2];
    #pragma unroll
    for (int ii = 0; ii < 4; ii++) { acc[ii][0] = make_float2(0.f, 0.f);
                                     acc[ii][1] = make_float2(0.f, 0.f); }

    for (int k0 = 0; k0 < H_; k0 += GBK) {
        // A tile: 64 rows x 16 k, transposed into As[k][m]
        {
            const int m = t >> 2, q = (t & 3) * 4;
            float4 v = *(const float4*)&emb[(m0 + m) * H_ + k0 + q];
            As[q + 0][m] = v.x; As[q + 1][m] = v.y;
            As[q + 2][m] = v.z; As[q + 3][m] = v.w;
        }
        // B tile: 16 k-rows x 64 n, natural layout
        {
            const int kk = t >> 4, nn = (t & 15) * 4;
            *(float4*)&Bs[kk][nn] = *(const float4*)&W[(k0 + kk) * HID_ + n0 + nn];
        }
        __syncthreads();

        #pragma unroll
        for (int k = 0; k < GBK; k++) {
            const float4 av = *(const float4*)&As[k][ty * 4];
            const float4 bv = *(const float4*)&Bs[k][tx * 4];
            const float2 b01 = make_float2(bv.x, bv.y);
            const float2 b23 = make_float2(bv.z, bv.w);
            const float ar[4] = {av.x, av.y, av.z, av.w};
            #pragma unroll
            for (int ii = 0; ii < 4; ii++) {
                const float2 ap = make_float2(ar[ii], ar[ii]);
                acc[ii][0] = ffma2(ap, b01, acc[ii][0]);
                acc[ii][1] = ffma2(ap, b23, acc[ii][1]);
            }
        }
        __syncthreads();
    }

    // Epilogue: add b1 (half 0 only), coalesced float4 stores
    const int n = n0 + tx * 4;
    float4 bias = make_float4(0.f, 0.f, 0.f, 0.f);
    if (half == 0) bias = *(const float4*)&b1[n];
    #pragma unroll
    for (int ii = 0; ii < 4; ii++) {
        const int m = m0 + ty * 4 + ii;
        float4 o;
        o.x = acc[ii][0].x + bias.x;
        o.y = acc[ii][0].y + bias.y;
        o.z = acc[ii][1].x + bias.z;
        o.w = acc[ii][1].y + bias.w;
        *(float4*)&out[m * HID_ + n] = o;
    }
}

// ---------------------------------------------------------------------------
// Kernel 2: pairwise  out[b,i,j] = sum_d relu(a[b,i,d]+c[b,j,d])*W2[d] + b2
// Tiles: 64x64 outputs per block, 256 threads, 4x4 per thread, d chunks of 16.
// Inner op per d: FADD (fma pipe) + FMNMX (alu pipe) + FFMA2 (fma pipe, packed j).
// ---------------------------------------------------------------------------
#define PTI 64
#define PTJ 64
#define PDK 16

__global__ void __launch_bounds__(256, 2)
pair_kernel(const float* __restrict__ W2, const float* __restrict__ b2,
            float* __restrict__ out)
{
    const int b  = blockIdx.z;
    const int i0 = blockIdx.y * PTI;
    const int j0 = blockIdx.x * PTJ;

    const float* __restrict__ A = g_a + b * (N_ * HID_);
    const float* __restrict__ C = g_c + b * (N_ * HID_);

    __shared__ float As[PDK][PTI + 4];
    __shared__ float Cs[PDK][PTJ + 4];
    __shared__ float Ws[HID_];

    const int t  = threadIdx.x;
    const int tx = t & 15;
    const int ty = t >> 4;

    Ws[t] = W2[t];   // 256 threads, 256 weights

    float2 acc[4][2];
    #pragma unroll
    for (int ii = 0; ii < 4; ii++) { acc[ii][0] = make_float2(0.f, 0.f);
                                     acc[ii][1] = make_float2(0.f, 0.f); }

    for (int d0 = 0; d0 < HID_; d0 += PDK) {
        {
            const int r = t >> 2, q = (t & 3) * 4;
            float4 va = *(const float4*)&A[(i0 + r) * HID_ + d0 + q];
            As[q + 0][r] = va.x; As[q + 1][r] = va.y;
            As[q + 2][r] = va.z; As[q + 3][r] = va.w;
            float4 vc = *(const float4*)&C[(j0 + r) * HID_ + d0 + q];
            Cs[q + 0][r] = vc.x; Cs[q + 1][r] = vc.y;
            Cs[q + 2][r] = vc.z; Cs[q + 3][r] = vc.w;
        }
        __syncthreads();

        #pragma unroll
        for (int dk = 0; dk < PDK; dk++) {
            const float w = Ws[d0 + dk];
            const float2 wp = make_float2(w, w);
            const float4 av = *(const float4*)&As[dk][ty * 4];
            const float4 cv = *(const float4*)&Cs[dk][tx * 4];
            const float ar[4] = {av.x, av.y, av.z, av.w};
            #pragma unroll
            for (int ii = 0; ii < 4; ii++) {
                const float a = ar[ii];
                float2 s0, s1;
                s0.x = fmaxf(a + cv.x, 0.f);
                s0.y = fmaxf(a + cv.y, 0.f);
                s1.x = fmaxf(a + cv.z, 0.f);
                s1.y = fmaxf(a + cv.w, 0.f);
                acc[ii][0] = ffma2(s0, wp, acc[ii][0]);
                acc[ii][1] = ffma2(s1, wp, acc[ii][1]);
            }
        }
        __syncthreads();
    }

    const float bb = b2[0];
    const int j = j0 + tx * 4;
    #pragma unroll
    for (int ii = 0; ii < 4; ii++) {
        const int i = i0 + ty * 4 + ii;
        float4 o;
        o.x = acc[ii][0].x + bb;
        o.y = acc[ii][0].y + bb;
        o.z = acc[ii][1].x + bb;
        o.w = acc[ii][1].y + bb;
        *(float4*)&out[((size_t)b * N_ + i) * N_ + j] = o;
    }
}

// ---------------------------------------------------------------------------
// Launch
// ---------------------------------------------------------------------------
extern "C" void kernel_launch(void* const* d_in, const int* in_sizes, int n_in,
                              void* d_out, int out_size)
{
    const float* emb = (const float*)d_in[0];
    const float* W1  = (const float*)d_in[1];
    const float* b1  = (const float*)d_in[2];
    const float* W2  = (const float*)d_in[3];
    const float* b2  = (const float*)d_in[4];
    float* out = (float*)d_out;

    // Stage 1: a = emb@Wa + b1, c = emb@Wb   (grid.z selects half)
    dim3 ggrid(HID_ / GBN, M_ / GBM, 2);       // 4 x 32 x 2 = 256 blocks
    gemm_kernel<<<ggrid, 256>>>(emb, W1, b1);

    // Stage 2: pairwise relu-dot
    dim3 pgrid(N_ / PTJ, N_ / PTI, B_);        // 8 x 8 x 4 = 256 blocks
    pair_kernel<<<pgrid, 256>>>(W2, b2, out);
}